// round 14
// baseline (speedup 1.0000x reference)
#include <cuda_runtime.h>
#include <cstdint>

#define B_  64
#define P_  2048
#define D_  1024
#define TILE_M 128
#define KC 32
#define NSTAGE (D_ / KC)        /* 32 stages */
#define PITCH 144               /* 9 16B-units/row */
#define A_OFF 0
#define B_OFF (TILE_M * PITCH)  /* 18432 */
#define STAGE_B 27648           /* A 18432 + B 9216 */
#define NBUF 4
#define SMEM_BYTES (NBUF * STAGE_B)        /* 110592 dynamic */
#define NCTAS ((P_ / TILE_M) * B_)         /* 1024 */

__device__ unsigned int g_key[B_ * B_];    /* order-preserving keys; 0 == -inf */
__device__ unsigned int g_count;           /* last-CTA counter; resets itself  */

__device__ __forceinline__ uint32_t smem_u32(const void* p) {
    uint32_t a;
    asm("{ .reg .u64 t; cvta.to.shared.u64 t, %1; cvt.u32.u64 %0, t; }" : "=r"(a) : "l"(p));
    return a;
}
/* one float4 (k 4p..4p+3) -> 4 fp16 = 8B @addr */
__device__ __forceinline__ void cvt_sts4h(uint32_t addr, float4 v) {
    uint32_t h0, h1;
    asm("cvt.rn.f16x2.f32 %0, %1, %2;" : "=r"(h0) : "f"(v.y), "f"(v.x));
    asm("cvt.rn.f16x2.f32 %0, %1, %2;" : "=r"(h1) : "f"(v.w), "f"(v.z));
    asm volatile("st.shared.v2.b32 [%0], {%1,%2};" :: "r"(addr), "r"(h0), "r"(h1) : "memory");
}
__device__ __forceinline__ void ldsm4(uint32_t* r, uint32_t addr) {
    asm volatile("ldmatrix.sync.aligned.m8n8.x4.shared.b16 {%0,%1,%2,%3}, [%4];"
                 : "=r"(r[0]), "=r"(r[1]), "=r"(r[2]), "=r"(r[3]) : "r"(addr));
}
__device__ __forceinline__ void mma16816(float* c, const uint32_t* a, const uint32_t* b) {
    asm volatile(
        "mma.sync.aligned.m16n8k16.row.col.f32.f16.f16.f32 "
        "{%0,%1,%2,%3}, {%4,%5,%6,%7}, {%8,%9}, {%0,%1,%2,%3};"
        : "+f"(c[0]), "+f"(c[1]), "+f"(c[2]), "+f"(c[3])
        : "r"(a[0]), "r"(a[1]), "r"(a[2]), "r"(a[3]), "r"(b[0]), "r"(b[1]));
}

/* Grid (16,64), 256 thr. sim[128p x 64c] single-pass fp16 HMMA.
   4-buffer smem ring, ONE barrier per TWO stages, single prefetch-reg set
   (mid-iteration LDG->STS gap covered by a full MMA stage). Warp-phase
   staggering; per-col max -> g_key; fused last-CTA hinge loss. */
__global__ __launch_bounds__(256, 2)
void fused_kernel(const float* __restrict__ im, const float* __restrict__ dis,
                  const void* __restrict__ lblRaw, float* __restrict__ out) {
    extern __shared__ __align__(128) char smem[];
    __shared__ int s_last, s_is64;
    __shared__ float rr[3][8];
    const uint32_t sb = smem_u32(smem);
    const int tid = threadIdx.x, lid = tid & 31, wid = tid >> 5;
    const int wm = wid & 3, wn = wid >> 2;
    const int b = blockIdx.y, pt = blockIdx.x;

    /* staging: row = tid>>3, part p = tid&7; 8 lanes cover one 128B gmem line */
    const int r0 = tid >> 3, p0 = tid & 7;
    const float* aG = im + ((size_t)(b * P_ + pt * TILE_M + r0)) * D_ + p0 * 4;
    const float* bG = dis + (size_t)r0 * D_ + p0 * 4;
    const uint32_t aS = sb + A_OFF + (uint32_t)(r0 * PITCH + (p0 >> 1) * 32 + (p0 & 1) * 8);
    const uint32_t bS = sb + B_OFF + (uint32_t)(r0 * PITCH + (p0 >> 1) * 32 + (p0 & 1) * 8);

    /* ldmatrix lane bases (k-octet-high = +32; sub s = +s*64) */
    const uint32_t aLd = sb + A_OFF + (uint32_t)((wm * 32 + (lid & 15)) * PITCH + (lid >> 4) * 32);
    const uint32_t bLd = sb + B_OFF + (uint32_t)((wn * 32 + (lid >> 4) * 8 + (lid & 7)) * PITCH
                                                 + ((lid >> 3) & 1) * 32);
    float acc[2][4][4];
    #pragma unroll
    for (int i = 0; i < 2; ++i)
        #pragma unroll
        for (int j = 0; j < 4; ++j)
            #pragma unroll
            for (int k = 0; k < 4; ++k) acc[i][j][k] = 0.f;

    float4 va[4], vb[2];
    const int sflip = (wid >> 1) & 1;

    auto do_sts = [&](uint32_t buf) {
        #pragma unroll
        for (int j = 0; j < 4; ++j) cvt_sts4h(buf + aS + j * 32 * PITCH, va[j]);
        #pragma unroll
        for (int j = 0; j < 2; ++j) cvt_sts4h(buf + bS + j * 32 * PITCH, vb[j]);
    };
    auto do_ldg = [&](int kt2) {
        const float* a2 = aG + kt2 * KC;
        const float* b2 = bG + kt2 * KC;
        #pragma unroll
        for (int j = 0; j < 4; ++j) va[j] = *(const float4*)(a2 + j * 32 * D_);
        #pragma unroll
        for (int j = 0; j < 2; ++j) vb[j] = *(const float4*)(b2 + j * 32 * D_);
    };
    auto do_mma = [&](uint32_t cur) {
        #pragma unroll
        for (int si = 0; si < 2; ++si) {
            const int s = si ^ sflip;
            uint32_t Ah[2][4], Bh[2][4];
            #pragma unroll
            for (int mt = 0; mt < 2; ++mt)
                ldsm4(Ah[mt], cur + aLd + mt * (16 * PITCH) + s * 64);
            #pragma unroll
            for (int h = 0; h < 2; ++h)
                ldsm4(Bh[h], cur + bLd + h * (16 * PITCH) + s * 64);
            #pragma unroll
            for (int mt = 0; mt < 2; ++mt)
                #pragma unroll
                for (int nt = 0; nt < 4; ++nt)
                    mma16816(acc[mt][nt], Ah[mt], &Bh[nt >> 1][(nt & 1) * 2]);
        }
    };

    /* prologue: stages 0,1 -> buffers 0,1; regs hold stage 2 */
    do_ldg(0);
    do_sts(0 * STAGE_B);
    do_ldg(1);
    do_sts(1 * STAGE_B);
    do_ldg(2);
    __syncthreads();

    for (int kt = 0; kt < NSTAGE; kt += 2) {
        const uint32_t c0 = (uint32_t)((kt & 3) * STAGE_B);
        const uint32_t c1 = (uint32_t)(((kt + 1) & 3) * STAGE_B);
        const uint32_t s2 = (uint32_t)(((kt + 2) & 3) * STAGE_B);
        const uint32_t s3 = (uint32_t)(((kt + 3) & 3) * STAGE_B);
        const bool h2 = (kt + 2 < NSTAGE), h3 = (kt + 3 < NSTAGE), h4 = (kt + 4 < NSTAGE);

        if ((wid & 1) == 0) {   /* even warps: stage first */
            if (h2) do_sts(s2);
            if (h3) do_ldg(kt + 3);
            do_mma(c0);
            if (h3) do_sts(s3);
            if (h4) do_ldg(kt + 4);
            do_mma(c1);
        } else {                /* odd warps: compute first */
            do_mma(c0);
            if (h2) do_sts(s2);
            if (h3) do_ldg(kt + 3);
            do_mma(c1);
            if (h3) do_sts(s3);
            if (h4) do_ldg(kt + 4);
        }
        __syncthreads();
    }

    /* epilogue: fragments -> smem -> per-column max -> atomicMax */
    float* red = (float*)smem;   /* [128][66] = 33792 <= 110592 */
    const int g = lid >> 2, t = lid & 3;
    #pragma unroll
    for (int mt = 0; mt < 2; ++mt) {
        const int rr0 = wm * 32 + mt * 16 + g;
        #pragma unroll
        for (int nt = 0; nt < 4; ++nt) {
            const int c = wn * 32 + nt * 8 + t * 2;
            red[rr0 * 66 + c]           = acc[mt][nt][0];
            red[rr0 * 66 + c + 1]       = acc[mt][nt][1];
            red[(rr0 + 8) * 66 + c]     = acc[mt][nt][2];
            red[(rr0 + 8) * 66 + c + 1] = acc[mt][nt][3];
        }
    }
    __syncthreads();
    if (tid < 64) {
        float m = -3.4e38f;
        #pragma unroll 8
        for (int r = 0; r < TILE_M; ++r) m = fmaxf(m, red[r * 66 + tid]);
        unsigned int k = __float_as_uint(m);
        k = (k & 0x80000000u) ? ~k : (k | 0x80000000u);
        atomicMax(&g_key[b * B_ + tid], k);
    }
    __syncthreads();
    if (tid == 0) {
        __threadfence();
        s_last = (atomicAdd(&g_count, 1u) == NCTAS - 1);
    }
    __syncthreads();
    if (!s_last) return;
    __threadfence();   /* acquire: all producers' g_key writes now visible */

    /* ---- last CTA: decode simMax, hinge loss, reset globals ---- */
    float* sm = (float*)smem;          /* [64][65] */
    int*   lab = (int*)(smem + 64 * 65 * 4);
    for (int e = tid; e < B_ * B_; e += 256) {
        const unsigned int u = g_key[e];
        sm[(e >> 6) * 65 + (e & 63)] =
            __uint_as_float((u & 0x80000000u) ? (u ^ 0x80000000u) : ~u);
    }
    if (tid < 32) {   /* int64 labels (values <64) have zero odd int32 words */
        int odd = ((const int*)lblRaw)[2 * tid + 1];
        unsigned mm = __ballot_sync(0xFFFFFFFFu, odd != 0);
        if (tid == 0) s_is64 = (mm == 0u);
    }
    __syncthreads();
    if (tid < B_)
        lab[tid] = s_is64 ? (int)((const long long*)lblRaw)[tid] : ((const int*)lblRaw)[tid];
    __syncthreads();
    for (int e = tid; e < B_ * B_; e += 256) g_key[e] = 0u;   /* reset */
    if (tid == 0) g_count = 0u;

    float s1 = 0.f, s2v = 0.f, n = 0.f;
    for (int e = tid; e < B_ * B_; e += 256) {
        const int i = e >> 6, j = e & 63;
        if (lab[i] != lab[j]) {
            n += 1.f;
            const float p = sm[i * 65 + i];
            s1  += fmaxf(sm[i * 65 + j] - p + 0.1f, 0.f);
            s2v += fmaxf(sm[j * 65 + i] - p + 0.1f, 0.f);
        }
    }
    #pragma unroll
    for (int o = 16; o > 0; o >>= 1) {
        s1  += __shfl_down_sync(0xFFFFFFFFu, s1, o);
        s2v += __shfl_down_sync(0xFFFFFFFFu, s2v, o);
        n   += __shfl_down_sync(0xFFFFFFFFu, n, o);
    }
    if (lid == 0) { rr[0][wid] = s1; rr[1][wid] = s2v; rr[2][wid] = n; }
    __syncthreads();
    if (tid == 0) {
        float a = 0.f, c = 0.f, d = 0.f;
        #pragma unroll
        for (int w = 0; w < 8; ++w) { a += rr[0][w]; c += rr[1][w]; d += rr[2][w]; }
        out[0] = (a + c) / (d + 1e-6f);
    }
}

extern "C" void kernel_launch(void* const* d_in, const int* in_sizes, int n_in,
                              void* d_out, int out_size) {
    (void)in_sizes; (void)n_in; (void)out_size;
    const float* im  = (const float*)d_in[0];
    const float* dis = (const float*)d_in[1];
    const void*  lbl = d_in[2];

    cudaFuncSetAttribute(fused_kernel, cudaFuncAttributeMaxDynamicSharedMemorySize, SMEM_BYTES);
    dim3 grid(P_ / TILE_M, B_);
    fused_kernel<<<grid, 256, SMEM_BYTES>>>(im, dis, lbl, (float*)d_out);
}

// round 15
// speedup vs baseline: 1.2720x; 1.2720x over previous
#include <cuda_runtime.h>
#include <cstdint>

#define B_  64
#define P_  2048
#define D_  1024
#define TILE_M 64
#define THREADS 128
#define KC 32
#define NSTAGE (D_ / KC)        /* 32 stages */
#define PITCH 80                /* 5 16B-units/row: 4 data + 1 pad; 5 coprime 8 */
#define A_OFF 0
#define B_OFF (TILE_M * PITCH)  /* 5120 */
#define STAGE_B (B_OFF + B_ * PITCH)       /* 10240 */
#define SMEM_BYTES (2 * STAGE_B)           /* 20480 dynamic */
#define NCTAS ((P_ / TILE_M) * B_)         /* 2048 */

__device__ unsigned int g_key[B_ * B_];    /* order-preserving keys; 0 == -inf */
__device__ unsigned int g_count;           /* last-CTA counter; resets itself  */

__device__ __forceinline__ uint32_t smem_u32(const void* p) {
    uint32_t a;
    asm("{ .reg .u64 t; cvta.to.shared.u64 t, %1; cvt.u32.u64 %0, t; }" : "=r"(a) : "l"(p));
    return a;
}
/* one float4 (k 4p..4p+3) -> 4 fp16 = 8B @addr */
__device__ __forceinline__ void cvt_sts4h(uint32_t addr, float4 v) {
    uint32_t h0, h1;
    asm("cvt.rn.f16x2.f32 %0, %1, %2;" : "=r"(h0) : "f"(v.y), "f"(v.x));
    asm("cvt.rn.f16x2.f32 %0, %1, %2;" : "=r"(h1) : "f"(v.w), "f"(v.z));
    asm volatile("st.shared.v2.b32 [%0], {%1,%2};" :: "r"(addr), "r"(h0), "r"(h1) : "memory");
}
__device__ __forceinline__ void ldsm4(uint32_t* r, uint32_t addr) {
    asm volatile("ldmatrix.sync.aligned.m8n8.x4.shared.b16 {%0,%1,%2,%3}, [%4];"
                 : "=r"(r[0]), "=r"(r[1]), "=r"(r[2]), "=r"(r[3]) : "r"(addr));
}
__device__ __forceinline__ void mma16816(float* c, const uint32_t* a, const uint32_t* b) {
    asm volatile(
        "mma.sync.aligned.m16n8k16.row.col.f32.f16.f16.f32 "
        "{%0,%1,%2,%3}, {%4,%5,%6,%7}, {%8,%9}, {%0,%1,%2,%3};"
        : "+f"(c[0]), "+f"(c[1]), "+f"(c[2]), "+f"(c[3])
        : "r"(a[0]), "r"(a[1]), "r"(a[2]), "r"(a[3]), "r"(b[0]), "r"(b[1]));
}

/* Grid (32,64), 128 thr, 5 CTAs/SM. sim[64p x 64c] single-pass fp16 HMMA,
   double-buffered smem, warp stagger; per-col max -> g_key; last CTA = loss.
   Row layout (PITCH=80): 16B units {k0-7, k8-15, k16-23, k24-31, pad}. */
__global__ __launch_bounds__(THREADS, 5)
void fused_kernel(const float* __restrict__ im, const float* __restrict__ dis,
                  const void* __restrict__ lblRaw, float* __restrict__ out) {
    extern __shared__ __align__(128) char smem[];
    __shared__ int s_last, s_is64;
    __shared__ float rr[3][4];
    const uint32_t sb = smem_u32(smem);
    const int tid = threadIdx.x, lid = tid & 31, wid = tid >> 5;
    const int wm = wid & 1, wn = wid >> 1;
    const int b = blockIdx.y, pt = blockIdx.x;

    /* staging: row r0 = tid>>3 (16 rows/slot), part p = tid&7 (one float4);
       4 slots advance rows by +16; 8 lanes cover one 128B gmem line */
    const int r0 = tid >> 3, p0 = tid & 7;
    const float* aG = im + ((size_t)(b * P_ + pt * TILE_M + r0)) * D_ + p0 * 4;
    const float* bG = dis + (size_t)r0 * D_ + p0 * 4;
    const uint32_t aS = sb + A_OFF + (uint32_t)(r0 * PITCH + p0 * 8);
    const uint32_t bS = sb + B_OFF + (uint32_t)(r0 * PITCH + p0 * 8);

    /* ldmatrix lane bases (k8-15 unit = +16; sub s = +s*32) */
    const uint32_t aLd = sb + A_OFF + (uint32_t)((wm * 32 + (lid & 15)) * PITCH + (lid >> 4) * 16);
    const uint32_t bLd = sb + B_OFF + (uint32_t)((wn * 32 + (lid >> 4) * 8 + (lid & 7)) * PITCH
                                                 + ((lid >> 3) & 1) * 16);
    float acc[2][4][4];
    #pragma unroll
    for (int i = 0; i < 2; ++i)
        #pragma unroll
        for (int j = 0; j < 4; ++j)
            #pragma unroll
            for (int k = 0; k < 4; ++k) acc[i][j][k] = 0.f;

    float4 va[4], vb[4];
    const int sflip = wid & 1;

    auto do_sts = [&](uint32_t nxt) {
        #pragma unroll
        for (int j = 0; j < 4; ++j) cvt_sts4h(nxt + aS + j * 16 * PITCH, va[j]);
        #pragma unroll
        for (int j = 0; j < 4; ++j) cvt_sts4h(nxt + bS + j * 16 * PITCH, vb[j]);
    };
    auto do_ldg = [&](int kt2) {
        const float* a2 = aG + kt2 * KC;
        const float* b2 = bG + kt2 * KC;
        #pragma unroll
        for (int j = 0; j < 4; ++j) va[j] = *(const float4*)(a2 + j * 16 * D_);
        #pragma unroll
        for (int j = 0; j < 4; ++j) vb[j] = *(const float4*)(b2 + j * 16 * D_);
    };
    auto do_mma = [&](uint32_t cur) {
        #pragma unroll
        for (int si = 0; si < 2; ++si) {
            const int s = si ^ sflip;
            uint32_t Ah[2][4], Bh[2][4];
            #pragma unroll
            for (int mt = 0; mt < 2; ++mt)
                ldsm4(Ah[mt], cur + aLd + mt * (16 * PITCH) + s * 32);
            #pragma unroll
            for (int h = 0; h < 2; ++h)
                ldsm4(Bh[h], cur + bLd + h * (16 * PITCH) + s * 32);
            #pragma unroll
            for (int mt = 0; mt < 2; ++mt)
                #pragma unroll
                for (int nt = 0; nt < 4; ++nt)
                    mma16816(acc[mt][nt], Ah[mt], &Bh[nt >> 1][(nt & 1) * 2]);
        }
    };

    /* prologue: stage 0 -> buf0; prefetch stage 1 */
    do_ldg(0);
    do_sts(0);
    do_ldg(1);
    __syncthreads();

    for (int kt = 0; kt < NSTAGE; ++kt) {
        const uint32_t cur = (uint32_t)((kt & 1) * STAGE_B);
        const uint32_t nxt = (uint32_t)(((kt + 1) & 1) * STAGE_B);
        const bool haveN = (kt + 1 < NSTAGE);
        const bool haveN2 = (kt + 2 < NSTAGE);

        if ((wid & 1) == 0) {       /* even warps: stage first, compute second */
            if (haveN)  do_sts(nxt);
            if (haveN2) do_ldg(kt + 2);
            do_mma(cur);
        } else {                    /* odd warps: compute first, stage second */
            do_mma(cur);
            if (haveN)  do_sts(nxt);
            if (haveN2) do_ldg(kt + 2);
        }
        __syncthreads();
    }

    /* epilogue: fragments -> smem -> per-column max -> atomicMax */
    float* red = (float*)smem;   /* [64][66] = 16896 <= 20480 */
    const int g = lid >> 2, t = lid & 3;
    #pragma unroll
    for (int mt = 0; mt < 2; ++mt) {
        const int rw = wm * 32 + mt * 16 + g;
        #pragma unroll
        for (int nt = 0; nt < 4; ++nt) {
            const int c = wn * 32 + nt * 8 + t * 2;
            red[rw * 66 + c]           = acc[mt][nt][0];
            red[rw * 66 + c + 1]       = acc[mt][nt][1];
            red[(rw + 8) * 66 + c]     = acc[mt][nt][2];
            red[(rw + 8) * 66 + c + 1] = acc[mt][nt][3];
        }
    }
    __syncthreads();
    if (tid < 64) {
        float m = -3.4e38f;
        #pragma unroll 8
        for (int r = 0; r < TILE_M; ++r) m = fmaxf(m, red[r * 66 + tid]);
        unsigned int k = __float_as_uint(m);
        k = (k & 0x80000000u) ? ~k : (k | 0x80000000u);
        atomicMax(&g_key[b * B_ + tid], k);
    }
    __syncthreads();
    if (tid == 0) {
        __threadfence();
        s_last = (atomicAdd(&g_count, 1u) == NCTAS - 1);
    }
    __syncthreads();
    if (!s_last) return;
    __threadfence();   /* acquire: all producers' g_key writes now visible */

    /* ---- last CTA: decode simMax, hinge loss, reset globals ---- */
    float* sm = (float*)smem;          /* [64][65] */
    int*   lab = (int*)(smem + 64 * 65 * 4);
    for (int e = tid; e < B_ * B_; e += THREADS) {
        const unsigned int u = g_key[e];
        sm[(e >> 6) * 65 + (e & 63)] =
            __uint_as_float((u & 0x80000000u) ? (u ^ 0x80000000u) : ~u);
    }
    if (tid < 32) {   /* int64 labels (values <64) have zero odd int32 words */
        int odd = ((const int*)lblRaw)[2 * tid + 1];
        unsigned mm = __ballot_sync(0xFFFFFFFFu, odd != 0);
        if (tid == 0) s_is64 = (mm == 0u);
    }
    __syncthreads();
    if (tid < B_)
        lab[tid] = s_is64 ? (int)((const long long*)lblRaw)[tid] : ((const int*)lblRaw)[tid];
    __syncthreads();
    for (int e = tid; e < B_ * B_; e += THREADS) g_key[e] = 0u;   /* reset */
    if (tid == 0) g_count = 0u;

    float s1 = 0.f, s2v = 0.f, n = 0.f;
    for (int e = tid; e < B_ * B_; e += THREADS) {
        const int i = e >> 6, j = e & 63;
        if (lab[i] != lab[j]) {
            n += 1.f;
            const float p = sm[i * 65 + i];
            s1  += fmaxf(sm[i * 65 + j] - p + 0.1f, 0.f);
            s2v += fmaxf(sm[j * 65 + i] - p + 0.1f, 0.f);
        }
    }
    #pragma unroll
    for (int o = 16; o > 0; o >>= 1) {
        s1  += __shfl_down_sync(0xFFFFFFFFu, s1, o);
        s2v += __shfl_down_sync(0xFFFFFFFFu, s2v, o);
        n   += __shfl_down_sync(0xFFFFFFFFu, n, o);
    }
    if (lid == 0) { rr[0][wid] = s1; rr[1][wid] = s2v; rr[2][wid] = n; }
    __syncthreads();
    if (tid == 0) {
        float a = 0.f, c = 0.f, d = 0.f;
        #pragma unroll
        for (int w = 0; w < 4; ++w) { a += rr[0][w]; c += rr[1][w]; d += rr[2][w]; }
        out[0] = (a + c) / (d + 1e-6f);
    }
}

extern "C" void kernel_launch(void* const* d_in, const int* in_sizes, int n_in,
                              void* d_out, int out_size) {
    (void)in_sizes; (void)n_in; (void)out_size;
    const float* im  = (const float*)d_in[0];
    const float* dis = (const float*)d_in[1];
    const void*  lbl = d_in[2];

    cudaFuncSetAttribute(fused_kernel, cudaFuncAttributeMaxDynamicSharedMemorySize, SMEM_BYTES);
    dim3 grid(P_ / TILE_M, B_);
    fused_kernel<<<grid, THREADS, SMEM_BYTES>>>(im, dis, lbl, (float*)d_out);
}